// round 11
// baseline (speedup 1.0000x reference)
#include <cuda_runtime.h>
#include <stdint.h>

#define NN   8192
#define NT   256
#define NB   (NN / NT)      // 32 blocks, thread-per-row
#define CPT  (NN / NT)      // 32 columns screened per thread
#define SCHUNK 2048         // slow-path compaction chunk

// Threefry-2x32-20, key=(0,42), partitionable path: counter=(0, i), out = o1 ^ o2.
__device__ __forceinline__ uint32_t threefry_bits_partitionable(uint32_t i)
{
    const uint32_t ks0 = 0u;
    const uint32_t ks1 = 42u;
    const uint32_t ks2 = 0x1BD11BDAu ^ ks0 ^ ks1;
    uint32_t x0 = 0u + ks0;
    uint32_t x1 = i  + ks1;
    #define TF_RND(r) { x0 += x1; x1 = (x1 << (r)) | (x1 >> (32 - (r))); x1 ^= x0; }
    TF_RND(13) TF_RND(15) TF_RND(26) TF_RND(6)
    x0 += ks1; x1 += ks2 + 1u;
    TF_RND(17) TF_RND(29) TF_RND(16) TF_RND(24)
    x0 += ks2; x1 += ks0 + 2u;
    TF_RND(13) TF_RND(15) TF_RND(26) TF_RND(6)
    x0 += ks0; x1 += ks1 + 3u;
    TF_RND(17) TF_RND(29) TF_RND(16) TF_RND(24)
    x0 += ks1; x1 += ks2 + 4u;
    TF_RND(13) TF_RND(15) TF_RND(26) TF_RND(6)
    x0 += ks2; x1 += ks0 + 5u;
    #undef TF_RND
    return x0 ^ x1;
}

// certain-zero: eps is exactly +0 in fp32 without evaluating transcendentals.
// taus>0 and -t/taus <= -110  =>  expf underflows to +0 (threshold ~ -103.97),
// and (1+tanhf(t)) is finite (t >= 110*taus > 0), so eps == +0 exactly.
__device__ __forceinline__ bool not_certain_zero(float t, float taus)
{
    return !((taus > 0.0f) && (t >= 110.0f * taus));
}

__global__ void __launch_bounds__(NT) k_fused(
        const float* __restrict__ w,
        const float* __restrict__ v,
        const float* __restrict__ I_ext,
        const float* __restrict__ E_L,
        const float* __restrict__ tau_m,
        const float* __restrict__ ts,
        const float* __restrict__ c,
        const float* __restrict__ Delta_u,
        const float* __restrict__ theta_v,
        const float* __restrict__ theta_inf,
        const float* __restrict__ J_theta,
        const float* __restrict__ spiked,
        const float* __restrict__ tau_theta,
        const float* __restrict__ tau_s,
        float* __restrict__ out)
{
    __shared__ int s_any;           // block-wide candidate flag
    __shared__ int s_n;             // slow-path chunk count
    __shared__ int s_cand[SCHUNK];  // slow-path candidate columns
    __shared__ float s_eps[SCHUNK]; // slow-path eps values

    int tid = threadIdx.x;
    int row = blockIdx.x * NT + tid;

    if (tid == 0) s_any = 0;
    __syncthreads();

    // ---- Phase 1: fast screen of all NN columns, 32 per thread, one MLP wave ----
    // ts/tau_s viewed as float4[NN/4]; thread covers float4 indices tid + k*NT.
    const float4* ts4 = (const float4*)ts;
    const float4* sa4 = (const float4*)tau_s;
    bool any = false;
    #pragma unroll
    for (int k = 0; k < CPT / 4; k++) {          // 8 iterations, fully unrolled
        float4 t4 = ts4[tid + k * NT];           // 16 independent loads total
        float4 s4 = sa4[tid + k * NT];
        any |= not_certain_zero(t4.x - 1.0f, s4.x);
        any |= not_certain_zero(t4.y - 1.0f, s4.y);
        any |= not_certain_zero(t4.z - 1.0f, s4.z);
        any |= not_certain_zero(t4.w - 1.0f, s4.w);
    }
    if (__ballot_sync(0xFFFFFFFFu, any) && (tid & 31) == 0) s_any = 1;
    __syncthreads();

    // ---- Phase 2: gather (general, exact; cold when no candidates) ----
    float acc = 0.0f;
    if (s_any) {
        const float* wrow = w + (size_t)row * NN;
        for (int base = 0; base < NN; base += SCHUNK) {
            if (tid == 0) s_n = 0;
            __syncthreads();
            for (int ccol = base + tid; ccol < base + SCHUNK; ccol += NT) {
                float t    = ts[ccol] - 1.0f;
                float taus = tau_s[ccol];
                if (not_certain_zero(t, taus)) {
                    float eps = (1.0f + tanhf(t)) * expf(-t / taus) / taus;
                    if (eps != 0.0f) {
                        int p = atomicAdd(&s_n, 1);
                        s_cand[p] = ccol;
                        s_eps[p]  = eps;
                    }
                }
            }
            __syncthreads();
            int n = s_n;
            for (int j = 0; j < n; j++) {
                int col  = s_cand[j];
                float we = (col == row) ? 0.0f : wrow[col];  // mask self-recurrence
                acc += we * s_eps[j];
            }
            __syncthreads();
        }
    }

    // ---- Phase 3: fully coalesced elementwise epilogue ----
    float th = theta_v[row]
             + (theta_inf[row] - theta_v[row] + J_theta[row] * spiked[row]) / tau_theta[row];

    float vi     = v[row];
    float v_next = vi + (E_L[row] - vi + I_ext[row]) / tau_m[row] + acc;
    float notref = (ts[row] > 2.0f) ? 1.0f : 0.0f;
    float lam    = notref * c[row] * expf((v_next - th) / Delta_u[row]);
    lam = fminf(fmaxf(lam, 0.0f), 1.0f);

    // JAX uniform: bitcast((bits >> 9) | 0x3F800000) - 1.0 ; bernoulli = u < p
    uint32_t bits = threefry_bits_partitionable((uint32_t)row);
    float u  = __uint_as_float((bits >> 9) | 0x3F800000u) - 1.0f;
    float sp = (u < lam) ? 1.0f : 0.0f;

    out[row]          = lam;                   // spikes_lambda
    out[NN + row]     = sp;                    // spiked_new
    out[2 * NN + row] = (1.0f - sp) * v_next;  // v_new (reset potential = 0)
}

extern "C" void kernel_launch(void* const* d_in, const int* in_sizes, int n_in,
                              void* d_out, int out_size)
{
    const float* I_ext     = (const float*)d_in[0];
    const float* w         = (const float*)d_in[1];
    const float* v         = (const float*)d_in[2];
    const float* spiked    = (const float*)d_in[3];
    const float* ts        = (const float*)d_in[4];
    const float* theta_v   = (const float*)d_in[5];
    const float* tau_m     = (const float*)d_in[6];
    const float* tau_s     = (const float*)d_in[7];
    const float* tau_theta = (const float*)d_in[8];
    const float* J_theta   = (const float*)d_in[9];
    const float* E_L       = (const float*)d_in[10];
    const float* c         = (const float*)d_in[11];
    const float* Delta_u   = (const float*)d_in[12];
    const float* theta_inf = (const float*)d_in[13];
    float* out = (float*)d_out;

    k_fused<<<NB, NT>>>(w, v, I_ext, E_L, tau_m, ts, c, Delta_u,
                        theta_v, theta_inf, J_theta, spiked, tau_theta, tau_s, out);
}

// round 14
// speedup vs baseline: 1.3077x; 1.3077x over previous
#include <cuda_runtime.h>
#include <stdint.h>

#define NN   8192
#define NT   256
#define NB   (NN / NT)      // 32 blocks, thread-per-row
#define SCHUNK 2048         // slow-path compaction chunk

// Threefry-2x32-20, key=(0,42), partitionable path: counter=(0, i), out = o1 ^ o2.
__device__ __forceinline__ uint32_t threefry_bits_partitionable(uint32_t i)
{
    const uint32_t ks0 = 0u;
    const uint32_t ks1 = 42u;
    const uint32_t ks2 = 0x1BD11BDAu ^ ks0 ^ ks1;
    uint32_t x0 = 0u + ks0;
    uint32_t x1 = i  + ks1;
    #define TF_RND(r) { x0 += x1; x1 = (x1 << (r)) | (x1 >> (32 - (r))); x1 ^= x0; }
    TF_RND(13) TF_RND(15) TF_RND(26) TF_RND(6)
    x0 += ks1; x1 += ks2 + 1u;
    TF_RND(17) TF_RND(29) TF_RND(16) TF_RND(24)
    x0 += ks2; x1 += ks0 + 2u;
    TF_RND(13) TF_RND(15) TF_RND(26) TF_RND(6)
    x0 += ks0; x1 += ks1 + 3u;
    TF_RND(17) TF_RND(29) TF_RND(16) TF_RND(24)
    x0 += ks1; x1 += ks2 + 4u;
    TF_RND(13) TF_RND(15) TF_RND(26) TF_RND(6)
    x0 += ks2; x1 += ks0 + 5u;
    #undef TF_RND
    return x0 ^ x1;
}

// certain-zero: eps == +0 in fp32 without transcendentals.
// taus>0 and t >= 110*taus  =>  expf(-t/taus) underflows to +0 (thr ~ -103.97),
// and (1+tanhf(t)) finite => eps exactly +0.
__device__ __forceinline__ bool not_certain_zero(float t, float taus)
{
    return !((taus > 0.0f) && (t >= 110.0f * taus));
}

__global__ void __launch_bounds__(NT) k_fused(
        const float* __restrict__ w,
        const float* __restrict__ v,
        const float* __restrict__ I_ext,
        const float* __restrict__ E_L,
        const float* __restrict__ tau_m,
        const float* __restrict__ ts,
        const float* __restrict__ c,
        const float* __restrict__ Delta_u,
        const float* __restrict__ theta_v,
        const float* __restrict__ theta_inf,
        const float* __restrict__ J_theta,
        const float* __restrict__ spiked,
        const float* __restrict__ tau_theta,
        const float* __restrict__ tau_s,
        float* __restrict__ out)
{
    __shared__ int   s_n;            // slow-path only
    __shared__ int   s_cand[SCHUNK];
    __shared__ float s_eps[SCHUNK];

    int tid = threadIdx.x;
    int row = blockIdx.x * NT + tid;

    // ---- Issue ALL loads up front: 12 epilogue scalars + 16 screen float4s ----
    float l_thv = theta_v[row];
    float l_thi = theta_inf[row];
    float l_Jt  = J_theta[row];
    float l_spk = spiked[row];
    float l_tth = tau_theta[row];
    float l_v   = v[row];
    float l_el  = E_L[row];
    float l_ie  = I_ext[row];
    float l_tm  = tau_m[row];
    float l_ts  = ts[row];
    float l_c   = c[row];
    float l_du  = Delta_u[row];

    const float4* ts4 = (const float4*)ts;
    const float4* sa4 = (const float4*)tau_s;
    float4 a[8], b[8];
    #pragma unroll
    for (int k = 0; k < 8; k++) {
        a[k] = ts4[tid + k * NT];
        b[k] = sa4[tid + k * NT];
    }

    // ---- Threefry while loads are in flight (pure ALU, independent) ----
    uint32_t bits = threefry_bits_partitionable((uint32_t)row);
    float u = __uint_as_float((bits >> 9) | 0x3F800000u) - 1.0f;

    // ---- Row-local epilogue pre-compute (independent of acc) ----
    float th     = l_thv + (l_thi - l_thv + l_Jt * l_spk) / l_tth;
    float v_base = l_v + (l_el - l_v + l_ie) / l_tm;   // v_next = v_base + acc
    float notref = (l_ts > 2.0f) ? 1.0f : 0.0f;

    // ---- Screen reduce (block covers all NN columns) ----
    bool any = false;
    #pragma unroll
    for (int k = 0; k < 8; k++) {
        any |= not_certain_zero(a[k].x - 1.0f, b[k].x);
        any |= not_certain_zero(a[k].y - 1.0f, b[k].y);
        any |= not_certain_zero(a[k].z - 1.0f, b[k].z);
        any |= not_certain_zero(a[k].w - 1.0f, b[k].w);
    }
    int blockany = __syncthreads_or(any ? 1 : 0);   // single barrier, no shared flag

    // ---- Slow path: general exact gather (cold when all eps certain-zero) ----
    float acc = 0.0f;
    if (blockany) {
        const float* wrow = w + (size_t)row * NN;
        for (int base = 0; base < NN; base += SCHUNK) {
            if (tid == 0) s_n = 0;
            __syncthreads();
            for (int ccol = base + tid; ccol < base + SCHUNK; ccol += NT) {
                float t    = ts[ccol] - 1.0f;
                float taus = tau_s[ccol];
                if (not_certain_zero(t, taus)) {
                    float eps = (1.0f + tanhf(t)) * expf(-t / taus) / taus;
                    if (eps != 0.0f) {
                        int p = atomicAdd(&s_n, 1);
                        s_cand[p] = ccol;
                        s_eps[p]  = eps;
                    }
                }
            }
            __syncthreads();
            int n = s_n;
            for (int j = 0; j < n; j++) {
                int col  = s_cand[j];
                float we = (col == row) ? 0.0f : wrow[col];  // mask self-recurrence
                acc += we * s_eps[j];
            }
            __syncthreads();
        }
    }

    // ---- Final epilogue ----
    float v_next = v_base + acc;
    float lam    = notref * l_c * expf((v_next - th) / l_du);
    lam = fminf(fmaxf(lam, 0.0f), 1.0f);
    float sp = (u < lam) ? 1.0f : 0.0f;   // JAX bernoulli: uniform < p

    out[row]          = lam;                   // spikes_lambda
    out[NN + row]     = sp;                    // spiked_new
    out[2 * NN + row] = (1.0f - sp) * v_next;  // v_new (reset potential = 0)
}

extern "C" void kernel_launch(void* const* d_in, const int* in_sizes, int n_in,
                              void* d_out, int out_size)
{
    const float* I_ext     = (const float*)d_in[0];
    const float* w         = (const float*)d_in[1];
    const float* v         = (const float*)d_in[2];
    const float* spiked    = (const float*)d_in[3];
    const float* ts        = (const float*)d_in[4];
    const float* theta_v   = (const float*)d_in[5];
    const float* tau_m     = (const float*)d_in[6];
    const float* tau_s     = (const float*)d_in[7];
    const float* tau_theta = (const float*)d_in[8];
    const float* J_theta   = (const float*)d_in[9];
    const float* E_L       = (const float*)d_in[10];
    const float* c         = (const float*)d_in[11];
    const float* Delta_u   = (const float*)d_in[12];
    const float* theta_inf = (const float*)d_in[13];
    float* out = (float*)d_out;

    k_fused<<<NB, NT>>>(w, v, I_ext, E_L, tau_m, ts, c, Delta_u,
                        theta_v, theta_inf, J_theta, spiked, tau_theta, tau_s, out);
}

// round 16
// speedup vs baseline: 1.3140x; 1.0048x over previous
#include <cuda_runtime.h>
#include <stdint.h>

#define NN   8192
#define NT   512
#define NB   (NN / NT)      // 16 blocks, thread-per-row
#define PAIRS (NN / 4 / NT) // 4 float4-pairs screened per thread
#define SCHUNK 2048         // slow-path compaction chunk

// Threefry-2x32-20, key=(0,42), partitionable path: counter=(0, i), out = o1 ^ o2.
__device__ __forceinline__ uint32_t threefry_bits_partitionable(uint32_t i)
{
    const uint32_t ks0 = 0u;
    const uint32_t ks1 = 42u;
    const uint32_t ks2 = 0x1BD11BDAu ^ ks0 ^ ks1;
    uint32_t x0 = 0u + ks0;
    uint32_t x1 = i  + ks1;
    #define TF_RND(r) { x0 += x1; x1 = (x1 << (r)) | (x1 >> (32 - (r))); x1 ^= x0; }
    TF_RND(13) TF_RND(15) TF_RND(26) TF_RND(6)
    x0 += ks1; x1 += ks2 + 1u;
    TF_RND(17) TF_RND(29) TF_RND(16) TF_RND(24)
    x0 += ks2; x1 += ks0 + 2u;
    TF_RND(13) TF_RND(15) TF_RND(26) TF_RND(6)
    x0 += ks0; x1 += ks1 + 3u;
    TF_RND(17) TF_RND(29) TF_RND(16) TF_RND(24)
    x0 += ks1; x1 += ks2 + 4u;
    TF_RND(13) TF_RND(15) TF_RND(26) TF_RND(6)
    x0 += ks2; x1 += ks0 + 5u;
    #undef TF_RND
    return x0 ^ x1;
}

// certain-zero: eps == +0 in fp32 without transcendentals.
// taus>0 and t >= 110*taus  =>  expf(-t/taus) underflows to +0 (thr ~ -103.97),
// and (1+tanhf(t)) finite => eps exactly +0.
__device__ __forceinline__ bool not_certain_zero(float t, float taus)
{
    return !((taus > 0.0f) && (t >= 110.0f * taus));
}

__global__ void __launch_bounds__(NT) k_fused(
        const float* __restrict__ w,
        const float* __restrict__ v,
        const float* __restrict__ I_ext,
        const float* __restrict__ E_L,
        const float* __restrict__ tau_m,
        const float* __restrict__ ts,
        const float* __restrict__ c,
        const float* __restrict__ Delta_u,
        const float* __restrict__ theta_v,
        const float* __restrict__ theta_inf,
        const float* __restrict__ J_theta,
        const float* __restrict__ spiked,
        const float* __restrict__ tau_theta,
        const float* __restrict__ tau_s,
        float* __restrict__ out)
{
    __shared__ int   s_n;            // slow-path only
    __shared__ int   s_cand[SCHUNK];
    __shared__ float s_eps[SCHUNK];

    int tid = threadIdx.x;
    int row = blockIdx.x * NT + tid;

    // ---- Issue ALL loads up front: 12 epilogue scalars + 8 screen float4s ----
    float l_thv = theta_v[row];
    float l_thi = theta_inf[row];
    float l_Jt  = J_theta[row];
    float l_spk = spiked[row];
    float l_tth = tau_theta[row];
    float l_v   = v[row];
    float l_el  = E_L[row];
    float l_ie  = I_ext[row];
    float l_tm  = tau_m[row];
    float l_ts  = ts[row];
    float l_c   = c[row];
    float l_du  = Delta_u[row];

    const float4* ts4 = (const float4*)ts;
    const float4* sa4 = (const float4*)tau_s;
    float4 a[PAIRS], b[PAIRS];
    #pragma unroll
    for (int k = 0; k < PAIRS; k++) {
        a[k] = ts4[tid + k * NT];
        b[k] = sa4[tid + k * NT];
    }

    // ---- Threefry while loads are in flight (pure ALU, independent) ----
    uint32_t bits = threefry_bits_partitionable((uint32_t)row);
    float u = __uint_as_float((bits >> 9) | 0x3F800000u) - 1.0f;

    // ---- Row-local epilogue pre-compute (independent of acc) ----
    float th     = l_thv + (l_thi - l_thv + l_Jt * l_spk) / l_tth;
    float v_base = l_v + (l_el - l_v + l_ie) / l_tm;   // v_next = v_base + acc
    float notref = (l_ts > 2.0f) ? 1.0f : 0.0f;

    // ---- Screen reduce (block covers all NN columns) ----
    bool any = false;
    #pragma unroll
    for (int k = 0; k < PAIRS; k++) {
        any |= not_certain_zero(a[k].x - 1.0f, b[k].x);
        any |= not_certain_zero(a[k].y - 1.0f, b[k].y);
        any |= not_certain_zero(a[k].z - 1.0f, b[k].z);
        any |= not_certain_zero(a[k].w - 1.0f, b[k].w);
    }
    int blockany = __syncthreads_or(any ? 1 : 0);   // single barrier

    // ---- Slow path: general exact gather (cold when all eps certain-zero) ----
    float acc = 0.0f;
    if (blockany) {
        const float* wrow = w + (size_t)row * NN;
        for (int base = 0; base < NN; base += SCHUNK) {
            if (tid == 0) s_n = 0;
            __syncthreads();
            for (int ccol = base + tid; ccol < base + SCHUNK; ccol += NT) {
                float t    = ts[ccol] - 1.0f;
                float taus = tau_s[ccol];
                if (not_certain_zero(t, taus)) {
                    float eps = (1.0f + tanhf(t)) * expf(-t / taus) / taus;
                    if (eps != 0.0f) {
                        int p = atomicAdd(&s_n, 1);
                        s_cand[p] = ccol;
                        s_eps[p]  = eps;
                    }
                }
            }
            __syncthreads();
            int n = s_n;
            for (int j = 0; j < n; j++) {
                int col  = s_cand[j];
                float we = (col == row) ? 0.0f : wrow[col];  // mask self-recurrence
                acc += we * s_eps[j];
            }
            __syncthreads();
        }
    }

    // ---- Final epilogue ----
    float v_next = v_base + acc;
    float lam    = notref * l_c * expf((v_next - th) / l_du);
    lam = fminf(fmaxf(lam, 0.0f), 1.0f);
    float sp = (u < lam) ? 1.0f : 0.0f;   // JAX bernoulli: uniform < p

    out[row]          = lam;                   // spikes_lambda
    out[NN + row]     = sp;                    // spiked_new
    out[2 * NN + row] = (1.0f - sp) * v_next;  // v_new (reset potential = 0)
}

extern "C" void kernel_launch(void* const* d_in, const int* in_sizes, int n_in,
                              void* d_out, int out_size)
{
    const float* I_ext     = (const float*)d_in[0];
    const float* w         = (const float*)d_in[1];
    const float* v         = (const float*)d_in[2];
    const float* spiked    = (const float*)d_in[3];
    const float* ts        = (const float*)d_in[4];
    const float* theta_v   = (const float*)d_in[5];
    const float* tau_m     = (const float*)d_in[6];
    const float* tau_s     = (const float*)d_in[7];
    const float* tau_theta = (const float*)d_in[8];
    const float* J_theta   = (const float*)d_in[9];
    const float* E_L       = (const float*)d_in[10];
    const float* c         = (const float*)d_in[11];
    const float* Delta_u   = (const float*)d_in[12];
    const float* theta_inf = (const float*)d_in[13];
    float* out = (float*)d_out;

    k_fused<<<NB, NT>>>(w, v, I_ext, E_L, tau_m, ts, c, Delta_u,
                        theta_v, theta_inf, J_theta, spiked, tau_theta, tau_s, out);
}